// round 4
// baseline (speedup 1.0000x reference)
#include <cuda_runtime.h>
#include <cstdint>
#include <math.h>

#define NE 160000
#define NN 10000
#define CC 64
#define HH 512
#define TLE 32
#define PI_F 3.14159265358979323846f

#define LATD_S 388    // floats/row: duplicated lat [32][192*2] + pad
#define HIDD_S 1028   // floats/row: duplicated hidden [32][512*2] + pad
#define XD_S   132    // duplicated x [32][64*2] + pad
#define MIX_S  132

typedef unsigned long long ull;

// ---- scratch ----
__device__ float g_x[NE * CC];
__device__ float g_u[NE * 3];
__device__ float g_env[NE];
__device__ float g_V[NE * CC * 3];
__device__ float g_rho0a[NN * CC];
__device__ float g_rho1a[NN * CC * 3];
__device__ float g_rho0b[NN * CC];
__device__ float g_rho1b[NN * CC * 3];

__device__ __forceinline__ float silu_f(float v) { return v / (1.f + __expf(-v)); }

// ---- packed f32x2 ops ----
__device__ __forceinline__ void ffma2(ull& c, ull a, ull b) {
    asm("fma.rn.f32x2 %0, %1, %2, %0;" : "+l"(c) : "l"(a), "l"(b));
}
__device__ __forceinline__ ull pk2(float v) {
    ull r; asm("mov.b64 %0, {%1, %1};" : "=l"(r) : "f"(v)); return r;
}
__device__ __forceinline__ float2 up2(ull v) {
    float2 f; asm("mov.b64 {%0, %1}, %2;" : "=f"(f.x), "=f"(f.y) : "l"(v)); return f;
}

// ============================================================
// phase2 helper: dx[32][64] += s_hidD[32, dup512] @ W2[512,64]
// 8-way k-split across warps, atomic reduce into s_dx
// ============================================================
__device__ __forceinline__ void mlp2_f32x2(const float* s_hidD,
                                           const float* __restrict__ W2,
                                           float* s_dx, int tid) {
    const int c0 = (tid & 3) * 16;
    const int i0 = ((tid >> 2) & 7) * 4;
    const int h0 = (tid >> 5) * 64;
    ull acc[4][8];
    #pragma unroll
    for (int r = 0; r < 4; r++)
        #pragma unroll
        for (int p = 0; p < 8; p++) acc[r][p] = 0ull;

    #pragma unroll 4
    for (int hh = 0; hh < 64; hh++) {
        int h = h0 + hh;
        ull a0 = *(const ull*)&s_hidD[(i0 + 0) * HIDD_S + 2 * h];
        ull a1 = *(const ull*)&s_hidD[(i0 + 1) * HIDD_S + 2 * h];
        ull a2 = *(const ull*)&s_hidD[(i0 + 2) * HIDD_S + 2 * h];
        ull a3 = *(const ull*)&s_hidD[(i0 + 3) * HIDD_S + 2 * h];
        const ulonglong2* wp = reinterpret_cast<const ulonglong2*>(W2 + h * CC + c0);
        ulonglong2 w0 = __ldg(wp + 0), w1 = __ldg(wp + 1);
        ulonglong2 w2 = __ldg(wp + 2), w3 = __ldg(wp + 3);
        ull b[8] = {w0.x, w0.y, w1.x, w1.y, w2.x, w2.y, w3.x, w3.y};
        #pragma unroll
        for (int p = 0; p < 8; p++) {
            ffma2(acc[0][p], a0, b[p]);
            ffma2(acc[1][p], a1, b[p]);
            ffma2(acc[2][p], a2, b[p]);
            ffma2(acc[3][p], a3, b[p]);
        }
    }
    #pragma unroll
    for (int r = 0; r < 4; r++)
        #pragma unroll
        for (int p = 0; p < 8; p++) {
            float2 v = up2(acc[r][p]);
            atomicAdd(&s_dx[(i0 + r) * CC + c0 + 2 * p],     v.x);
            atomicAdd(&s_dx[(i0 + r) * CC + c0 + 2 * p + 1], v.y);
        }
}

// ============================================================
// small GEMM helper: o[2 rows][8 cols] = A_dup[32, dup64] @ B[64, ldb]
// ============================================================
template <int LDA>
__device__ __forceinline__ void gemm64_2x8(const float* sA,
                                           const float* __restrict__ B,
                                           int ldb, int i0, int c0,
                                           float2 o[2][4]) {
    ull acc[2][4];
    #pragma unroll
    for (int r = 0; r < 2; r++)
        #pragma unroll
        for (int p = 0; p < 4; p++) acc[r][p] = 0ull;
    #pragma unroll 4
    for (int k = 0; k < 64; k++) {
        ull a0 = *(const ull*)&sA[(i0 + 0) * LDA + 2 * k];
        ull a1 = *(const ull*)&sA[(i0 + 1) * LDA + 2 * k];
        const ulonglong2* wp = reinterpret_cast<const ulonglong2*>(B + k * ldb + c0);
        ulonglong2 w0 = __ldg(wp + 0), w1 = __ldg(wp + 1);
        ull b[4] = {w0.x, w0.y, w1.x, w1.y};
        #pragma unroll
        for (int p = 0; p < 4; p++) {
            ffma2(acc[0][p], a0, b[p]);
            ffma2(acc[1][p], a1, b[p]);
        }
    }
    #pragma unroll
    for (int r = 0; r < 2; r++)
        #pragma unroll
        for (int p = 0; p < 4; p++) o[r][p] = up2(acc[r][p]);
}

// env-projection + scatter to rho
template <int LDA>
__device__ __forceinline__ void scatter_env(const float* sA,
                                            const float* __restrict__ Wenv,
                                            const int* s_send, const float* s_u3,
                                            float* rho0w, float* rho1w, int tid) {
    if (tid >= 128) return;
    const int c0 = (tid & 7) * 8;
    const int i0 = (tid >> 3) * 2;
    float2 o[2][4];
    gemm64_2x8<LDA>(sA, Wenv, CC, i0, c0, o);
    #pragma unroll
    for (int r = 0; r < 2; r++) {
        int i = i0 + r;
        int sn = s_send[i];
        float ux = s_u3[i * 3 + 0], uy = s_u3[i * 3 + 1], uz = s_u3[i * 3 + 2];
        #pragma unroll
        for (int p = 0; p < 4; p++) {
            #pragma unroll
            for (int q = 0; q < 2; q++) {
                int c = c0 + 2 * p + q;
                float v = (q ? o[r][p].y : o[r][p].x) * (1.f / 3.f);
                atomicAdd(&rho0w[sn * CC + c], v);
                int rb = (sn * CC + c) * 3;
                atomicAdd(&rho1w[rb + 0], v * ux);
                atomicAdd(&rho1w[rb + 1], v * uy);
                atomicAdd(&rho1w[rb + 2], v * uz);
            }
        }
    }
}

// ============================================================
__global__ void k_zero(float* __restrict__ out) {
    int idx = blockIdx.x * 256 + threadIdx.x;
    if (idx < NN) out[idx] = 0.f;
    if (idx < NN * CC) { g_rho0a[idx] = 0.f; g_rho0b[idx] = 0.f; }
    if (idx < NN * CC * 3) { g_rho1a[idx] = 0.f; g_rho1b[idx] = 0.f; }
}

// ============================================================
// K1: embed (geometry + 12->512->64 MLP) + vinit + scatter layer0
// ============================================================
__global__ __launch_bounds__(256) void k_embed(
    const float* __restrict__ pos,
    const int* __restrict__ species,
    const int* __restrict__ senders,
    const int* __restrict__ receivers,
    const float* __restrict__ W1,    // [12,512]
    const float* __restrict__ W2,    // [512,64]
    const float* __restrict__ Wv,    // [64,64]
    const float* __restrict__ Wenv0) // [64,64]
{
    extern __shared__ float sm[];
    float* s_hidD = sm;                        // [32][HIDD_S]
    float* s_xD   = sm + TLE * HIDD_S;         // [32][XD_S]
    float* s_dx   = s_xD + TLE * XD_S;         // [32][64]
    __shared__ float s_feat[32][13];
    __shared__ float s_env[32];
    __shared__ float s_u3[32 * 3];
    __shared__ int   s_send[32];

    const int tid = threadIdx.x;
    const int e0 = blockIdx.x * TLE;

    if (tid < 32) {
        int e = e0 + tid;
        int sn = senders[e], rc = receivers[e];
        s_send[tid] = sn;
        float rx = pos[rc * 3 + 0] - pos[sn * 3 + 0];
        float ry = pos[rc * 3 + 1] - pos[sn * 3 + 1];
        float rz = pos[rc * 3 + 2] - pos[sn * 3 + 2];
        float d = sqrtf(rx * rx + ry * ry + rz * rz);
        float ds = fmaxf(d, 1e-6f);
        float inv = 1.f / ds;
        float ux = rx * inv, uy = ry * inv, uz = rz * inv;
        g_u[e * 3 + 0] = ux; g_u[e * 3 + 1] = uy; g_u[e * 3 + 2] = uz;
        s_u3[tid * 3 + 0] = ux; s_u3[tid * 3 + 1] = uy; s_u3[tid * 3 + 2] = uz;
        float xc = d * 0.5f;
        float env = 0.f;
        if (xc < 1.f) { float tt = 1.f - xc * xc; env = tt * tt; }
        g_env[e] = env;
        s_env[tid] = env;
        float pref = env * inv;
        float ang = PI_F * xc;
        #pragma unroll
        for (int n = 1; n <= 8; n++) s_feat[tid][n - 1] = pref * __sinf((float)n * ang);
        float ssn = (species[sn] == 1) ? 1.f : 0.f;
        float src = (species[rc] == 1) ? 1.f : 0.f;
        s_feat[tid][8] = 1.f - ssn; s_feat[tid][9] = ssn;
        s_feat[tid][10] = 1.f - src; s_feat[tid][11] = src;
    }
    // zero dx
    #pragma unroll
    for (int q = 0; q < 8; q++) s_dx[tid + 256 * q] = 0.f;
    __syncthreads();

    // phase A: hiddenD = silu(feat @ W1), duplicated store (scalar, K=12)
    #pragma unroll
    for (int j = 0; j < 2; j++) {
        int h = tid + 256 * j;
        float w1r[12];
        #pragma unroll
        for (int k = 0; k < 12; k++) w1r[k] = W1[k * HH + h];
        #pragma unroll 4
        for (int i = 0; i < 32; i++) {
            float acc = 0.f;
            #pragma unroll
            for (int k = 0; k < 12; k++) acc += s_feat[i][k] * w1r[k];
            *(ull*)&s_hidD[i * HIDD_S + 2 * h] = pk2(silu_f(acc));
        }
    }
    __syncthreads();

    // phase B: x = (hidden @ W2) * env
    mlp2_f32x2(s_hidD, W2, s_dx, tid);
    __syncthreads();

    #pragma unroll
    for (int q = 0; q < 8; q++) {
        int idx = tid + 256 * q;
        int i = idx >> 6, c = idx & 63;
        float x = s_dx[i * CC + c] * s_env[i];
        g_x[(e0 + i) * CC + c] = x;
        *(ull*)&s_xD[i * XD_S + 2 * c] = pk2(x);
    }
    __syncthreads();

    // vinit: V = (x @ Wv) outer u    (threads 0..127)
    if (tid < 128) {
        const int c0 = (tid & 7) * 8;
        const int i0 = (tid >> 3) * 2;
        float2 o[2][4];
        gemm64_2x8<XD_S>(s_xD, Wv, CC, i0, c0, o);
        #pragma unroll
        for (int r = 0; r < 2; r++) {
            int i = i0 + r, e = e0 + i;
            float ux = s_u3[i * 3 + 0], uy = s_u3[i * 3 + 1], uz = s_u3[i * 3 + 2];
            #pragma unroll
            for (int p = 0; p < 4; p++) {
                #pragma unroll
                for (int q = 0; q < 2; q++) {
                    int c = c0 + 2 * p + q;
                    float v = q ? o[r][p].y : o[r][p].x;
                    int vb = (e * CC + c) * 3;
                    g_V[vb + 0] = v * ux;
                    g_V[vb + 1] = v * uy;
                    g_V[vb + 2] = v * uz;
                }
            }
        }
    }
    // scatter layer-0 density
    scatter_env<XD_S>(s_xD, Wenv0, s_send, s_u3, g_rho0a, g_rho1a, tid);
}

// ============================================================
// K2: full layer — gather+TP, f32x2 MLP, mix, V update, epilogue
// ============================================================
__global__ __launch_bounds__(256) void k_layer(
    const float* __restrict__ W1,    // [192,512]
    const float* __restrict__ W2,    // [512,64]
    const float* __restrict__ Wm,    // [64,128]
    const float* __restrict__ WenvN, // [64,64] (mode 0)
    const float* __restrict__ Wout,  // [64]    (mode 1)
    const int* __restrict__ senders,
    const int* __restrict__ receivers,
    const float* __restrict__ rho0r,
    const float* __restrict__ rho1r,
    float* __restrict__ rho0w,
    float* __restrict__ rho1w,
    float* __restrict__ out,
    int mode)
{
    extern __shared__ float sm[];
    float* s_latD = sm;                         // [32][LATD_S]
    float* s_hidD = sm + TLE * LATD_S;          // [32][HIDD_S]
    float* s_dx   = s_hidD + TLE * HIDD_S;      // [32][64]
    float* s_mix  = s_hidD;                     // overlay after phase2: [32][MIX_S]
    __shared__ int   s_send[32], s_recv[32];
    __shared__ float s_env[32], s_u3[32 * 3];

    const int tid = threadIdx.x;
    const int e0 = blockIdx.x * TLE;

    if (tid < 32) {
        int e = e0 + tid;
        s_send[tid] = senders[e];
        s_recv[tid] = receivers[e];
        s_env[tid] = g_env[e];
        s_u3[tid * 3 + 0] = g_u[e * 3 + 0];
        s_u3[tid * 3 + 1] = g_u[e * 3 + 1];
        s_u3[tid * 3 + 2] = g_u[e * 3 + 2];
    }
    // zero dx
    #pragma unroll
    for (int q = 0; q < 8; q++) s_dx[tid + 256 * q] = 0.f;
    __syncthreads();

    // ---- build lat_in (duplicated) = [x | tp_scal | rho0_e] ----
    #pragma unroll
    for (int q = 0; q < 8; q++) {
        int idx = tid + 256 * q;
        int i = idx >> 6, c = idx & 63;
        int e = e0 + i, sn = s_send[i];
        float xv = g_x[e * CC + c];
        float r0 = rho0r[sn * CC + c];
        int rb = (sn * CC + c) * 3;
        float r1x = rho1r[rb], r1y = rho1r[rb + 1], r1z = rho1r[rb + 2];
        int vb = (e * CC + c) * 3;
        float Vx = g_V[vb], Vy = g_V[vb + 1], Vz = g_V[vb + 2];
        float tp = Vx * r1x + Vy * r1y + Vz * r1z;
        *(ull*)&s_latD[i * LATD_S + 2 * c]         = pk2(xv);
        *(ull*)&s_latD[i * LATD_S + 2 * (64 + c)]  = pk2(tp);
        *(ull*)&s_latD[i * LATD_S + 2 * (128 + c)] = pk2(r0);
    }
    __syncthreads();

    // ---- phase 1: hiddenD = silu(lat @ W1), f32x2, 4 rows x 16 cols/thread ----
    {
        const int c0 = (tid & 31) * 16;
        const int i0 = (tid >> 5) * 4;
        ull acc[4][8];
        #pragma unroll
        for (int r = 0; r < 4; r++)
            #pragma unroll
            for (int p = 0; p < 8; p++) acc[r][p] = 0ull;

        #pragma unroll 2
        for (int k = 0; k < 192; k++) {
            ull a0 = *(const ull*)&s_latD[(i0 + 0) * LATD_S + 2 * k];
            ull a1 = *(const ull*)&s_latD[(i0 + 1) * LATD_S + 2 * k];
            ull a2 = *(const ull*)&s_latD[(i0 + 2) * LATD_S + 2 * k];
            ull a3 = *(const ull*)&s_latD[(i0 + 3) * LATD_S + 2 * k];
            const ulonglong2* wp = reinterpret_cast<const ulonglong2*>(W1 + k * HH + c0);
            ulonglong2 w0 = __ldg(wp + 0), w1 = __ldg(wp + 1);
            ulonglong2 w2 = __ldg(wp + 2), w3 = __ldg(wp + 3);
            ull b[8] = {w0.x, w0.y, w1.x, w1.y, w2.x, w2.y, w3.x, w3.y};
            #pragma unroll
            for (int p = 0; p < 8; p++) {
                ffma2(acc[0][p], a0, b[p]);
                ffma2(acc[1][p], a1, b[p]);
                ffma2(acc[2][p], a2, b[p]);
                ffma2(acc[3][p], a3, b[p]);
            }
        }
        // silu + duplicated store: [s0,s0,s1,s1] per acc pair -> float4
        #pragma unroll
        for (int r = 0; r < 4; r++)
            #pragma unroll
            for (int p = 0; p < 8; p++) {
                float2 v = up2(acc[r][p]);
                float4 d;
                d.x = d.y = silu_f(v.x);
                d.z = d.w = silu_f(v.y);
                *(float4*)&s_hidD[(i0 + r) * HIDD_S + 2 * (c0 + 2 * p)] = d;
            }
    }
    __syncthreads();

    // ---- phase 2: dx = hidden @ W2 ----
    mlp2_f32x2(s_hidD, W2, s_dx, tid);
    __syncthreads();

    // x update
    const float inv_s2 = 0.70710678118654752f;
    #pragma unroll
    for (int q = 0; q < 8; q++) {
        int idx = tid + 256 * q;
        int i = idx >> 6, c = idx & 63;
        float xn = (s_latD[i * LATD_S + 2 * c] + s_dx[i * CC + c] * s_env[i]) * inv_s2;
        *(ull*)&s_latD[i * LATD_S + 2 * c] = pk2(xn);
        g_x[(e0 + i) * CC + c] = xn;
    }
    __syncthreads();

    if (mode == 0) {
        // ---- phase 3a: mix = x_new @ Wm  (2 rows x 8 cols/thread) ----
        {
            const int c0 = (tid & 15) * 8;
            const int i0 = (tid >> 4) * 2;
            float2 o[2][4];
            gemm64_2x8<LATD_S>(s_latD, Wm, 2 * CC, i0, c0, o);
            __syncthreads();   // s_mix overlays s_hidD; ensure phase2 reads done
            #pragma unroll
            for (int r = 0; r < 2; r++)
                #pragma unroll
                for (int p = 0; p < 4; p++) {
                    s_mix[(i0 + r) * MIX_S + c0 + 2 * p]     = o[r][p].x;
                    s_mix[(i0 + r) * MIX_S + c0 + 2 * p + 1] = o[r][p].y;
                }
        }
        __syncthreads();

        // ---- phase 3b: V = mix1 * (V * rho0) + mix2 * cross(V, rho1) ----
        #pragma unroll
        for (int q = 0; q < 8; q++) {
            int idx = tid + 256 * q;
            int i = idx >> 6, c = idx & 63;
            int e = e0 + i, sn = s_send[i];
            int vb = (e * CC + c) * 3;
            float Vx = g_V[vb], Vy = g_V[vb + 1], Vz = g_V[vb + 2];
            int rb = (sn * CC + c) * 3;
            float r1x = rho1r[rb], r1y = rho1r[rb + 1], r1z = rho1r[rb + 2];
            float r0 = s_latD[i * LATD_S + 2 * (128 + c)];
            float m1 = s_mix[i * MIX_S + c];
            float m2 = s_mix[i * MIX_S + 64 + c];
            float cx = Vy * r1z - Vz * r1y;
            float cy = Vz * r1x - Vx * r1z;
            float cz = Vx * r1y - Vy * r1x;
            g_V[vb + 0] = m1 * Vx * r0 + m2 * cx;
            g_V[vb + 1] = m1 * Vy * r0 + m2 * cy;
            g_V[vb + 2] = m1 * Vz * r0 + m2 * cz;
        }
        // ---- scatter next-layer density ----
        scatter_env<LATD_S>(s_latD, WenvN, s_send, s_u3, rho0w, rho1w, tid);
    } else {
        // ---- final energy readout ----
        int i = tid >> 3, k8 = tid & 7;
        float p = 0.f;
        #pragma unroll
        for (int q = 0; q < 8; q++) {
            int c = k8 + 8 * q;
            p += s_latD[i * LATD_S + 2 * c] * __ldg(&Wout[c]);
        }
        p += __shfl_xor_sync(0xffffffffu, p, 1);
        p += __shfl_xor_sync(0xffffffffu, p, 2);
        p += __shfl_xor_sync(0xffffffffu, p, 4);
        if ((tid & 7) == 0)
            atomicAdd(&out[s_recv[i]], p * s_env[i] * (1.f / 3.f));
    }
}

// ============================================================
extern "C" void kernel_launch(void* const* d_in, const int* in_sizes, int n_in,
                              void* d_out, int out_size)
{
    const float* pos     = (const float*)d_in[0];
    const float* W_emb1  = (const float*)d_in[1];
    const float* W_emb2  = (const float*)d_in[2];
    const float* W_v     = (const float*)d_in[3];
    const float* W_env   = (const float*)d_in[4];
    const float* W_lat1  = (const float*)d_in[5];
    const float* W_lat2  = (const float*)d_in[6];
    const float* W_mix   = (const float*)d_in[7];
    const float* W_out   = (const float*)d_in[8];
    const int*   species = (const int*)d_in[9];
    const int*   senders = (const int*)d_in[10];
    const int*   recv    = (const int*)d_in[11];
    float* out = (float*)d_out;

    const int smem_embed = (TLE * HIDD_S + TLE * XD_S + TLE * CC) * sizeof(float);   // 156672
    const int smem_layer = (TLE * LATD_S + TLE * HIDD_S + TLE * CC) * sizeof(float); // 189440
    cudaFuncSetAttribute(k_embed, cudaFuncAttributeMaxDynamicSharedMemorySize, smem_embed);
    cudaFuncSetAttribute(k_layer, cudaFuncAttributeMaxDynamicSharedMemorySize, smem_layer);

    float* rho0a; cudaGetSymbolAddress((void**)&rho0a, g_rho0a);
    float* rho1a; cudaGetSymbolAddress((void**)&rho1a, g_rho1a);
    float* rho0b; cudaGetSymbolAddress((void**)&rho0b, g_rho0b);
    float* rho1b; cudaGetSymbolAddress((void**)&rho1b, g_rho1b);

    k_zero<<<(NN * CC * 3 + 255) / 256, 256>>>(out);
    k_embed<<<NE / TLE, 256, smem_embed>>>(pos, species, senders, recv,
                                           W_emb1, W_emb2, W_v, W_env);
    // layer 0: read rhoA, scatter rhoB for layer 1
    k_layer<<<NE / TLE, 256, smem_layer>>>(
        W_lat1, W_lat2, W_mix, W_env + CC * CC, nullptr,
        senders, recv, rho0a, rho1a, rho0b, rho1b, out, 0);
    // layer 1 (final): read rhoB, energy readout
    k_layer<<<NE / TLE, 256, smem_layer>>>(
        W_lat1 + 192 * HH, W_lat2 + HH * CC, W_mix + CC * 2 * CC, nullptr, W_out,
        senders, recv, rho0b, rho1b, nullptr, nullptr, out, 1);
}

// round 5
// speedup vs baseline: 1.0515x; 1.0515x over previous
#include <cuda_runtime.h>
#include <cstdint>
#include <math.h>

#define NE 160000
#define NN 10000
#define CC 64
#define HH 512
#define TLE 32
#define PI_F 3.14159265358979323846f

#define LATD_S 388    // floats/row: duplicated lat [32][192*2] + pad
#define HIDD_S 1028   // floats/row: duplicated hidden [32][512*2] + pad
#define XD_S   132    // duplicated x [32][64*2] + pad
#define MIX_S  132

typedef unsigned long long ull;

// ---- scratch ----
__device__ float g_x[NE * CC];
__device__ float g_u[NE * 3];
__device__ float g_env[NE];
__device__ float g_V[NE * CC * 3];
__device__ float g_rho0a[NN * CC];
__device__ float g_rho1a[NN * CC * 3];
__device__ float g_rho0b[NN * CC];
__device__ float g_rho1b[NN * CC * 3];

__device__ __forceinline__ float silu_f(float v) { return v / (1.f + __expf(-v)); }

// ---- packed f32x2 ops ----
__device__ __forceinline__ void ffma2(ull& c, ull a, ull b) {
    asm("fma.rn.f32x2 %0, %1, %2, %0;" : "+l"(c) : "l"(a), "l"(b));
}
__device__ __forceinline__ ull pk2(float v) {
    ull r; asm("mov.b64 %0, {%1, %1};" : "=l"(r) : "f"(v)); return r;
}
__device__ __forceinline__ float2 up2(ull v) {
    float2 f; asm("mov.b64 {%0, %1}, %2;" : "=f"(f.x), "=f"(f.y) : "l"(v)); return f;
}

// ============================================================
// phase2 helper: dx[32][64] += s_hidD[32, dup512] @ W2[512,64]
// 8-way k-split across warps, atomic reduce into s_dx
// ============================================================
__device__ __forceinline__ void mlp2_f32x2(const float* s_hidD,
                                           const float* __restrict__ W2,
                                           float* s_dx, int tid) {
    const int c0 = (tid & 3) * 16;
    const int i0 = ((tid >> 2) & 7) * 4;
    const int h0 = (tid >> 5) * 64;
    ull acc[4][8];
    #pragma unroll
    for (int r = 0; r < 4; r++)
        #pragma unroll
        for (int p = 0; p < 8; p++) acc[r][p] = 0ull;

    #pragma unroll 4
    for (int hh = 0; hh < 64; hh++) {
        int h = h0 + hh;
        ull a0 = *(const ull*)&s_hidD[(i0 + 0) * HIDD_S + 2 * h];
        ull a1 = *(const ull*)&s_hidD[(i0 + 1) * HIDD_S + 2 * h];
        ull a2 = *(const ull*)&s_hidD[(i0 + 2) * HIDD_S + 2 * h];
        ull a3 = *(const ull*)&s_hidD[(i0 + 3) * HIDD_S + 2 * h];
        const ulonglong2* wp = reinterpret_cast<const ulonglong2*>(W2 + h * CC + c0);
        ulonglong2 w0 = __ldg(wp + 0), w1 = __ldg(wp + 1);
        ulonglong2 w2 = __ldg(wp + 2), w3 = __ldg(wp + 3);
        ull b[8] = {w0.x, w0.y, w1.x, w1.y, w2.x, w2.y, w3.x, w3.y};
        #pragma unroll
        for (int p = 0; p < 8; p++) {
            ffma2(acc[0][p], a0, b[p]);
            ffma2(acc[1][p], a1, b[p]);
            ffma2(acc[2][p], a2, b[p]);
            ffma2(acc[3][p], a3, b[p]);
        }
    }
    #pragma unroll
    for (int r = 0; r < 4; r++)
        #pragma unroll
        for (int p = 0; p < 8; p++) {
            float2 v = up2(acc[r][p]);
            atomicAdd(&s_dx[(i0 + r) * CC + c0 + 2 * p],     v.x);
            atomicAdd(&s_dx[(i0 + r) * CC + c0 + 2 * p + 1], v.y);
        }
}

// ============================================================
// small GEMM helper: o[2 rows][8 cols] = A_dup[32, dup64] @ B[64, ldb]
// ============================================================
template <int LDA>
__device__ __forceinline__ void gemm64_2x8(const float* sA,
                                           const float* __restrict__ B,
                                           int ldb, int i0, int c0,
                                           float2 o[2][4]) {
    ull acc[2][4];
    #pragma unroll
    for (int r = 0; r < 2; r++)
        #pragma unroll
        for (int p = 0; p < 4; p++) acc[r][p] = 0ull;
    #pragma unroll 4
    for (int k = 0; k < 64; k++) {
        ull a0 = *(const ull*)&sA[(i0 + 0) * LDA + 2 * k];
        ull a1 = *(const ull*)&sA[(i0 + 1) * LDA + 2 * k];
        const ulonglong2* wp = reinterpret_cast<const ulonglong2*>(B + k * ldb + c0);
        ulonglong2 w0 = __ldg(wp + 0), w1 = __ldg(wp + 1);
        ull b[4] = {w0.x, w0.y, w1.x, w1.y};
        #pragma unroll
        for (int p = 0; p < 4; p++) {
            ffma2(acc[0][p], a0, b[p]);
            ffma2(acc[1][p], a1, b[p]);
        }
    }
    #pragma unroll
    for (int r = 0; r < 2; r++)
        #pragma unroll
        for (int p = 0; p < 4; p++) o[r][p] = up2(acc[r][p]);
}

// env-projection + scatter to rho
template <int LDA>
__device__ __forceinline__ void scatter_env(const float* sA,
                                            const float* __restrict__ Wenv,
                                            const int* s_send, const float* s_u3,
                                            float* rho0w, float* rho1w, int tid) {
    if (tid >= 128) return;
    const int c0 = (tid & 7) * 8;
    const int i0 = (tid >> 3) * 2;
    float2 o[2][4];
    gemm64_2x8<LDA>(sA, Wenv, CC, i0, c0, o);
    #pragma unroll
    for (int r = 0; r < 2; r++) {
        int i = i0 + r;
        int sn = s_send[i];
        float ux = s_u3[i * 3 + 0], uy = s_u3[i * 3 + 1], uz = s_u3[i * 3 + 2];
        #pragma unroll
        for (int p = 0; p < 4; p++) {
            #pragma unroll
            for (int q = 0; q < 2; q++) {
                int c = c0 + 2 * p + q;
                float v = (q ? o[r][p].y : o[r][p].x) * (1.f / 3.f);
                atomicAdd(&rho0w[sn * CC + c], v);
                int rb = (sn * CC + c) * 3;
                atomicAdd(&rho1w[rb + 0], v * ux);
                atomicAdd(&rho1w[rb + 1], v * uy);
                atomicAdd(&rho1w[rb + 2], v * uz);
            }
        }
    }
}

// ============================================================
__global__ void k_zero(float* __restrict__ out) {
    int idx = blockIdx.x * 256 + threadIdx.x;
    if (idx < NN) out[idx] = 0.f;
    if (idx < NN * CC) { g_rho0a[idx] = 0.f; g_rho0b[idx] = 0.f; }
    if (idx < NN * CC * 3) { g_rho1a[idx] = 0.f; g_rho1b[idx] = 0.f; }
}

// ============================================================
// K1: embed (geometry + 12->512->64 MLP) + vinit + scatter layer0
// ============================================================
__global__ __launch_bounds__(256) void k_embed(
    const float* __restrict__ pos,
    const int* __restrict__ species,
    const int* __restrict__ senders,
    const int* __restrict__ receivers,
    const float* __restrict__ W1,    // [12,512]
    const float* __restrict__ W2,    // [512,64]
    const float* __restrict__ Wv,    // [64,64]
    const float* __restrict__ Wenv0) // [64,64]
{
    extern __shared__ float sm[];
    float* s_hidD = sm;                        // [32][HIDD_S]
    float* s_xD   = sm + TLE * HIDD_S;         // [32][XD_S]
    float* s_dx   = s_xD + TLE * XD_S;         // [32][64]
    __shared__ float s_feat[32][13];
    __shared__ float s_env[32];
    __shared__ float s_u3[32 * 3];
    __shared__ int   s_send[32];

    const int tid = threadIdx.x;
    const int e0 = blockIdx.x * TLE;

    if (tid < 32) {
        int e = e0 + tid;
        int sn = senders[e], rc = receivers[e];
        s_send[tid] = sn;
        float rx = pos[rc * 3 + 0] - pos[sn * 3 + 0];
        float ry = pos[rc * 3 + 1] - pos[sn * 3 + 1];
        float rz = pos[rc * 3 + 2] - pos[sn * 3 + 2];
        float d = sqrtf(rx * rx + ry * ry + rz * rz);
        float ds = fmaxf(d, 1e-6f);
        float inv = 1.f / ds;
        float ux = rx * inv, uy = ry * inv, uz = rz * inv;
        g_u[e * 3 + 0] = ux; g_u[e * 3 + 1] = uy; g_u[e * 3 + 2] = uz;
        s_u3[tid * 3 + 0] = ux; s_u3[tid * 3 + 1] = uy; s_u3[tid * 3 + 2] = uz;
        float xc = d * 0.5f;
        float env = 0.f;
        if (xc < 1.f) { float tt = 1.f - xc * xc; env = tt * tt; }
        g_env[e] = env;
        s_env[tid] = env;
        float pref = env * inv;
        float ang = PI_F * xc;
        #pragma unroll
        for (int n = 1; n <= 8; n++) s_feat[tid][n - 1] = pref * __sinf((float)n * ang);
        float ssn = (species[sn] == 1) ? 1.f : 0.f;
        float src = (species[rc] == 1) ? 1.f : 0.f;
        s_feat[tid][8] = 1.f - ssn; s_feat[tid][9] = ssn;
        s_feat[tid][10] = 1.f - src; s_feat[tid][11] = src;
    }
    // zero dx
    #pragma unroll
    for (int q = 0; q < 8; q++) s_dx[tid + 256 * q] = 0.f;
    __syncthreads();

    // phase A: hiddenD = silu(feat @ W1), duplicated store (scalar, K=12)
    #pragma unroll
    for (int j = 0; j < 2; j++) {
        int h = tid + 256 * j;
        float w1r[12];
        #pragma unroll
        for (int k = 0; k < 12; k++) w1r[k] = W1[k * HH + h];
        #pragma unroll 4
        for (int i = 0; i < 32; i++) {
            float acc = 0.f;
            #pragma unroll
            for (int k = 0; k < 12; k++) acc += s_feat[i][k] * w1r[k];
            *(ull*)&s_hidD[i * HIDD_S + 2 * h] = pk2(silu_f(acc));
        }
    }
    __syncthreads();

    // phase B: x = (hidden @ W2) * env
    mlp2_f32x2(s_hidD, W2, s_dx, tid);
    __syncthreads();

    #pragma unroll
    for (int q = 0; q < 8; q++) {
        int idx = tid + 256 * q;
        int i = idx >> 6, c = idx & 63;
        float x = s_dx[i * CC + c] * s_env[i];
        g_x[(e0 + i) * CC + c] = x;
        *(ull*)&s_xD[i * XD_S + 2 * c] = pk2(x);
    }
    __syncthreads();

    // vinit: V = (x @ Wv) outer u    (threads 0..127)
    if (tid < 128) {
        const int c0 = (tid & 7) * 8;
        const int i0 = (tid >> 3) * 2;
        float2 o[2][4];
        gemm64_2x8<XD_S>(s_xD, Wv, CC, i0, c0, o);
        #pragma unroll
        for (int r = 0; r < 2; r++) {
            int i = i0 + r, e = e0 + i;
            float ux = s_u3[i * 3 + 0], uy = s_u3[i * 3 + 1], uz = s_u3[i * 3 + 2];
            #pragma unroll
            for (int p = 0; p < 4; p++) {
                #pragma unroll
                for (int q = 0; q < 2; q++) {
                    int c = c0 + 2 * p + q;
                    float v = q ? o[r][p].y : o[r][p].x;
                    int vb = (e * CC + c) * 3;
                    g_V[vb + 0] = v * ux;
                    g_V[vb + 1] = v * uy;
                    g_V[vb + 2] = v * uz;
                }
            }
        }
    }
    // scatter layer-0 density
    scatter_env<XD_S>(s_xD, Wenv0, s_send, s_u3, g_rho0a, g_rho1a, tid);
}

// ============================================================
// K2: full layer — gather+TP, f32x2 MLP, mix, V update, epilogue
// ============================================================
__global__ __launch_bounds__(256) void k_layer(
    const float* __restrict__ W1,    // [192,512]
    const float* __restrict__ W2,    // [512,64]
    const float* __restrict__ Wm,    // [64,128]
    const float* __restrict__ WenvN, // [64,64] (mode 0)
    const float* __restrict__ Wout,  // [64]    (mode 1)
    const int* __restrict__ senders,
    const int* __restrict__ receivers,
    const float* __restrict__ rho0r,
    const float* __restrict__ rho1r,
    float* __restrict__ rho0w,
    float* __restrict__ rho1w,
    float* __restrict__ out,
    int mode)
{
    extern __shared__ float sm[];
    float* s_latD = sm;                         // [32][LATD_S]
    float* s_hidD = sm + TLE * LATD_S;          // [32][HIDD_S]
    float* s_dx   = s_hidD + TLE * HIDD_S;      // [32][64]
    float* s_mix  = s_hidD;                     // overlay after phase2: [32][MIX_S]
    __shared__ int   s_send[32], s_recv[32];
    __shared__ float s_env[32], s_u3[32 * 3];

    const int tid = threadIdx.x;
    const int e0 = blockIdx.x * TLE;

    if (tid < 32) {
        int e = e0 + tid;
        s_send[tid] = senders[e];
        s_recv[tid] = receivers[e];
        s_env[tid] = g_env[e];
        s_u3[tid * 3 + 0] = g_u[e * 3 + 0];
        s_u3[tid * 3 + 1] = g_u[e * 3 + 1];
        s_u3[tid * 3 + 2] = g_u[e * 3 + 2];
    }
    // zero dx
    #pragma unroll
    for (int q = 0; q < 8; q++) s_dx[tid + 256 * q] = 0.f;
    __syncthreads();

    // ---- build lat_in (duplicated) = [x | tp_scal | rho0_e] ----
    #pragma unroll
    for (int q = 0; q < 8; q++) {
        int idx = tid + 256 * q;
        int i = idx >> 6, c = idx & 63;
        int e = e0 + i, sn = s_send[i];
        float xv = g_x[e * CC + c];
        float r0 = rho0r[sn * CC + c];
        int rb = (sn * CC + c) * 3;
        float r1x = rho1r[rb], r1y = rho1r[rb + 1], r1z = rho1r[rb + 2];
        int vb = (e * CC + c) * 3;
        float Vx = g_V[vb], Vy = g_V[vb + 1], Vz = g_V[vb + 2];
        float tp = Vx * r1x + Vy * r1y + Vz * r1z;
        *(ull*)&s_latD[i * LATD_S + 2 * c]         = pk2(xv);
        *(ull*)&s_latD[i * LATD_S + 2 * (64 + c)]  = pk2(tp);
        *(ull*)&s_latD[i * LATD_S + 2 * (128 + c)] = pk2(r0);
    }
    __syncthreads();

    // ---- phase 1: hiddenD = silu(lat @ W1), f32x2, 4 rows x 16 cols/thread ----
    {
        const int c0 = (tid & 31) * 16;
        const int i0 = (tid >> 5) * 4;
        ull acc[4][8];
        #pragma unroll
        for (int r = 0; r < 4; r++)
            #pragma unroll
            for (int p = 0; p < 8; p++) acc[r][p] = 0ull;

        #pragma unroll 2
        for (int k = 0; k < 192; k++) {
            ull a0 = *(const ull*)&s_latD[(i0 + 0) * LATD_S + 2 * k];
            ull a1 = *(const ull*)&s_latD[(i0 + 1) * LATD_S + 2 * k];
            ull a2 = *(const ull*)&s_latD[(i0 + 2) * LATD_S + 2 * k];
            ull a3 = *(const ull*)&s_latD[(i0 + 3) * LATD_S + 2 * k];
            const ulonglong2* wp = reinterpret_cast<const ulonglong2*>(W1 + k * HH + c0);
            ulonglong2 w0 = __ldg(wp + 0), w1 = __ldg(wp + 1);
            ulonglong2 w2 = __ldg(wp + 2), w3 = __ldg(wp + 3);
            ull b[8] = {w0.x, w0.y, w1.x, w1.y, w2.x, w2.y, w3.x, w3.y};
            #pragma unroll
            for (int p = 0; p < 8; p++) {
                ffma2(acc[0][p], a0, b[p]);
                ffma2(acc[1][p], a1, b[p]);
                ffma2(acc[2][p], a2, b[p]);
                ffma2(acc[3][p], a3, b[p]);
            }
        }
        // silu + duplicated store: [s0,s0,s1,s1] per acc pair -> float4
        #pragma unroll
        for (int r = 0; r < 4; r++)
            #pragma unroll
            for (int p = 0; p < 8; p++) {
                float2 v = up2(acc[r][p]);
                float4 d;
                d.x = d.y = silu_f(v.x);
                d.z = d.w = silu_f(v.y);
                *(float4*)&s_hidD[(i0 + r) * HIDD_S + 2 * (c0 + 2 * p)] = d;
            }
    }
    __syncthreads();

    // ---- phase 2: dx = hidden @ W2 ----
    mlp2_f32x2(s_hidD, W2, s_dx, tid);
    __syncthreads();

    // x update
    const float inv_s2 = 0.70710678118654752f;
    #pragma unroll
    for (int q = 0; q < 8; q++) {
        int idx = tid + 256 * q;
        int i = idx >> 6, c = idx & 63;
        float xn = (s_latD[i * LATD_S + 2 * c] + s_dx[i * CC + c] * s_env[i]) * inv_s2;
        *(ull*)&s_latD[i * LATD_S + 2 * c] = pk2(xn);
        g_x[(e0 + i) * CC + c] = xn;
    }
    __syncthreads();

    if (mode == 0) {
        // ---- phase 3a: mix = x_new @ Wm  (2 rows x 8 cols/thread) ----
        {
            const int c0 = (tid & 15) * 8;
            const int i0 = (tid >> 4) * 2;
            float2 o[2][4];
            gemm64_2x8<LATD_S>(s_latD, Wm, 2 * CC, i0, c0, o);
            __syncthreads();   // s_mix overlays s_hidD; ensure phase2 reads done
            #pragma unroll
            for (int r = 0; r < 2; r++)
                #pragma unroll
                for (int p = 0; p < 4; p++) {
                    s_mix[(i0 + r) * MIX_S + c0 + 2 * p]     = o[r][p].x;
                    s_mix[(i0 + r) * MIX_S + c0 + 2 * p + 1] = o[r][p].y;
                }
        }
        __syncthreads();

        // ---- phase 3b: V = mix1 * (V * rho0) + mix2 * cross(V, rho1) ----
        #pragma unroll
        for (int q = 0; q < 8; q++) {
            int idx = tid + 256 * q;
            int i = idx >> 6, c = idx & 63;
            int e = e0 + i, sn = s_send[i];
            int vb = (e * CC + c) * 3;
            float Vx = g_V[vb], Vy = g_V[vb + 1], Vz = g_V[vb + 2];
            int rb = (sn * CC + c) * 3;
            float r1x = rho1r[rb], r1y = rho1r[rb + 1], r1z = rho1r[rb + 2];
            float r0 = s_latD[i * LATD_S + 2 * (128 + c)];
            float m1 = s_mix[i * MIX_S + c];
            float m2 = s_mix[i * MIX_S + 64 + c];
            float cx = Vy * r1z - Vz * r1y;
            float cy = Vz * r1x - Vx * r1z;
            float cz = Vx * r1y - Vy * r1x;
            g_V[vb + 0] = m1 * Vx * r0 + m2 * cx;
            g_V[vb + 1] = m1 * Vy * r0 + m2 * cy;
            g_V[vb + 2] = m1 * Vz * r0 + m2 * cz;
        }
        // ---- scatter next-layer density ----
        scatter_env<LATD_S>(s_latD, WenvN, s_send, s_u3, rho0w, rho1w, tid);
    } else {
        // ---- final energy readout ----
        int i = tid >> 3, k8 = tid & 7;
        float p = 0.f;
        #pragma unroll
        for (int q = 0; q < 8; q++) {
            int c = k8 + 8 * q;
            p += s_latD[i * LATD_S + 2 * c] * __ldg(&Wout[c]);
        }
        p += __shfl_xor_sync(0xffffffffu, p, 1);
        p += __shfl_xor_sync(0xffffffffu, p, 2);
        p += __shfl_xor_sync(0xffffffffu, p, 4);
        if ((tid & 7) == 0)
            atomicAdd(&out[s_recv[i]], p * s_env[i] * (1.f / 3.f));
    }
}

// ============================================================
extern "C" void kernel_launch(void* const* d_in, const int* in_sizes, int n_in,
                              void* d_out, int out_size)
{
    const float* pos     = (const float*)d_in[0];
    const float* W_emb1  = (const float*)d_in[1];
    const float* W_emb2  = (const float*)d_in[2];
    const float* W_v     = (const float*)d_in[3];
    const float* W_env   = (const float*)d_in[4];
    const float* W_lat1  = (const float*)d_in[5];
    const float* W_lat2  = (const float*)d_in[6];
    const float* W_mix   = (const float*)d_in[7];
    const float* W_out   = (const float*)d_in[8];
    const int*   species = (const int*)d_in[9];
    const int*   senders = (const int*)d_in[10];
    const int*   recv    = (const int*)d_in[11];
    float* out = (float*)d_out;

    const int smem_embed = (TLE * HIDD_S + TLE * XD_S + TLE * CC) * sizeof(float);   // 156672
    const int smem_layer = (TLE * LATD_S + TLE * HIDD_S + TLE * CC) * sizeof(float); // 189440
    cudaFuncSetAttribute(k_embed, cudaFuncAttributeMaxDynamicSharedMemorySize, smem_embed);
    cudaFuncSetAttribute(k_layer, cudaFuncAttributeMaxDynamicSharedMemorySize, smem_layer);

    float* rho0a; cudaGetSymbolAddress((void**)&rho0a, g_rho0a);
    float* rho1a; cudaGetSymbolAddress((void**)&rho1a, g_rho1a);
    float* rho0b; cudaGetSymbolAddress((void**)&rho0b, g_rho0b);
    float* rho1b; cudaGetSymbolAddress((void**)&rho1b, g_rho1b);

    k_zero<<<(NN * CC * 3 + 255) / 256, 256>>>(out);
    k_embed<<<NE / TLE, 256, smem_embed>>>(pos, species, senders, recv,
                                           W_emb1, W_emb2, W_v, W_env);
    // layer 0: read rhoA, scatter rhoB for layer 1
    k_layer<<<NE / TLE, 256, smem_layer>>>(
        W_lat1, W_lat2, W_mix, W_env + CC * CC, nullptr,
        senders, recv, rho0a, rho1a, rho0b, rho1b, out, 0);
    // layer 1 (final): read rhoB, energy readout
    k_layer<<<NE / TLE, 256, smem_layer>>>(
        W_lat1 + 192 * HH, W_lat2 + HH * CC, W_mix + CC * 2 * CC, nullptr, W_out,
        senders, recv, rho0b, rho1b, nullptr, nullptr, out, 1);
}

// round 6
// speedup vs baseline: 2.9960x; 2.8493x over previous
#include <cuda_runtime.h>
#include <cstdint>
#include <math.h>

#define NE 160000
#define NN 10000
#define CC 64
#define HH 512
#define TLE 64
#define NTHR 512
#define PI_F 3.14159265358979323846f

#define LAT_S 196
#define HID_S 516
#define X_S   68
#define MIX_S 132

// split-weight buffer offsets (floats)
#define OFF_EMB2 0
#define OFF_V    32768
#define OFF_ENV  36864
#define OFF_LAT1 45056
#define OFF_LAT2 241664
#define OFF_MIX  307200
#define TOTW     323584

__device__ float g_Whi[TOTW];
__device__ float g_Wlo[TOTW];
__device__ float g_x[NE * CC];
__device__ float g_u[NE * 3];
__device__ float g_env[NE];
__device__ float g_V[NE * CC * 3];
__device__ float g_rho0a[NN * CC];
__device__ float g_rho1a[NN * CC * 3];
__device__ float g_rho0b[NN * CC];
__device__ float g_rho1b[NN * CC * 3];

__device__ __forceinline__ float silu_f(float v) { return v / (1.f + __expf(-v)); }

__device__ __forceinline__ void mma8(float c[4], uint32_t a0, uint32_t a1, uint32_t a2,
                                     uint32_t a3, uint32_t b0, uint32_t b1) {
    asm volatile(
        "mma.sync.aligned.m16n8k8.row.col.f32.tf32.tf32.f32 "
        "{%0,%1,%2,%3},{%4,%5,%6,%7},{%8,%9},{%0,%1,%2,%3};\n"
        : "+f"(c[0]), "+f"(c[1]), "+f"(c[2]), "+f"(c[3])
        : "r"(a0), "r"(a1), "r"(a2), "r"(a3), "r"(b0), "r"(b1));
}

__device__ __forceinline__ void tf32split(float v, uint32_t& hi, uint32_t& lo) {
    uint32_t h;
    asm("cvt.rna.tf32.f32 %0, %1;" : "=r"(h) : "f"(v));
    hi = h;
    lo = __float_as_uint(v - __uint_as_float(h));
}

// ============================================================
// 3xTF32 GEMM: acc[MT][NT][4] += A[r0.., K] @ B[K, ldb] (cols n0..)
// A fp32 in smem (split on the fly), B pre-split (Bhi/Blo global).
// Warp fragment layout: thread (g=lane>>2, t=lane&3).
// ============================================================
template <int MT, int NT, int KS, int LDA>
__device__ __forceinline__ void gemm3(const float* sA, int r0,
                                      const float* __restrict__ Bhi,
                                      const float* __restrict__ Blo,
                                      int ldb, int n0, int g, int t,
                                      float (&acc)[MT][NT][4]) {
    #pragma unroll
    for (int m = 0; m < MT; m++)
        #pragma unroll
        for (int j = 0; j < NT; j++)
            #pragma unroll
            for (int q = 0; q < 4; q++) acc[m][j][q] = 0.f;

    #pragma unroll 4
    for (int ks = 0; ks < KS; ks++) {
        int kb = ks * 8;
        uint32_t ah[MT][4], al[MT][4];
        #pragma unroll
        for (int m = 0; m < MT; m++) {
            int rb = r0 + m * 16;
            tf32split(sA[(rb + g)     * LDA + kb + t],     ah[m][0], al[m][0]);
            tf32split(sA[(rb + 8 + g) * LDA + kb + t],     ah[m][1], al[m][1]);
            tf32split(sA[(rb + g)     * LDA + kb + t + 4], ah[m][2], al[m][2]);
            tf32split(sA[(rb + 8 + g) * LDA + kb + t + 4], ah[m][3], al[m][3]);
        }
        #pragma unroll
        for (int j = 0; j < NT; j++) {
            int col = n0 + 8 * j + g;
            uint32_t bh0 = __float_as_uint(__ldg(&Bhi[(kb + t)     * ldb + col]));
            uint32_t bh1 = __float_as_uint(__ldg(&Bhi[(kb + t + 4) * ldb + col]));
            uint32_t bl0 = __float_as_uint(__ldg(&Blo[(kb + t)     * ldb + col]));
            uint32_t bl1 = __float_as_uint(__ldg(&Blo[(kb + t + 4) * ldb + col]));
            #pragma unroll
            for (int m = 0; m < MT; m++) {
                mma8(acc[m][j], ah[m][0], ah[m][1], ah[m][2], ah[m][3], bh0, bh1);
                mma8(acc[m][j], ah[m][0], ah[m][1], ah[m][2], ah[m][3], bl0, bl1);
                mma8(acc[m][j], al[m][0], al[m][1], al[m][2], al[m][3], bh0, bh1);
            }
        }
    }
}

// ============================================================
__global__ void k_zero(float* __restrict__ out) {
    int idx = blockIdx.x * 256 + threadIdx.x;
    if (idx < NN) out[idx] = 0.f;
    if (idx < NN * CC) { g_rho0a[idx] = 0.f; g_rho0b[idx] = 0.f; }
    if (idx < NN * CC * 3) { g_rho1a[idx] = 0.f; g_rho1b[idx] = 0.f; }
}

__global__ void k_prep(const float* __restrict__ emb2, const float* __restrict__ wv,
                       const float* __restrict__ wenv, const float* __restrict__ lat1,
                       const float* __restrict__ lat2, const float* __restrict__ wmix) {
    int i = blockIdx.x * 256 + threadIdx.x;
    if (i >= TOTW) return;
    float v;
    if (i < OFF_V)         v = emb2[i];
    else if (i < OFF_ENV)  v = wv[i - OFF_V];
    else if (i < OFF_LAT1) v = wenv[i - OFF_ENV];
    else if (i < OFF_LAT2) v = lat1[i - OFF_LAT1];
    else if (i < OFF_MIX)  v = lat2[i - OFF_LAT2];
    else                   v = wmix[i - OFF_MIX];
    uint32_t hi, lo;
    tf32split(v, hi, lo);
    g_Whi[i] = __uint_as_float(hi);
    g_Wlo[i] = __uint_as_float(lo);
}

// ============================================================
// K1: embed (geometry + 12->512->64 MLP) + vinit + scatter layer0
// 64 edges/block, 512 threads
// ============================================================
__global__ __launch_bounds__(NTHR, 1) void k_embed(
    const float* __restrict__ pos,
    const int* __restrict__ species,
    const int* __restrict__ senders,
    const int* __restrict__ receivers,
    const float* __restrict__ W1)    // [12,512] fp32
{
    extern __shared__ float sm[];
    float* s_hid = sm;                    // [64][HID_S]
    float* s_x   = sm + TLE * HID_S;      // [64][X_S]
    __shared__ float s_feat[TLE][13];
    __shared__ float s_env[TLE];
    __shared__ float s_u3[TLE * 3];
    __shared__ int   s_send[TLE];

    const int tid = threadIdx.x;
    const int warp = tid >> 5, lane = tid & 31;
    const int g = lane >> 2, t = lane & 3;
    const int e0 = blockIdx.x * TLE;

    if (tid < TLE) {
        int e = e0 + tid;
        int sn = senders[e], rc = receivers[e];
        s_send[tid] = sn;
        float rx = pos[rc * 3 + 0] - pos[sn * 3 + 0];
        float ry = pos[rc * 3 + 1] - pos[sn * 3 + 1];
        float rz = pos[rc * 3 + 2] - pos[sn * 3 + 2];
        float d = sqrtf(rx * rx + ry * ry + rz * rz);
        float ds = fmaxf(d, 1e-6f);
        float inv = 1.f / ds;
        float ux = rx * inv, uy = ry * inv, uz = rz * inv;
        g_u[e * 3 + 0] = ux; g_u[e * 3 + 1] = uy; g_u[e * 3 + 2] = uz;
        s_u3[tid * 3 + 0] = ux; s_u3[tid * 3 + 1] = uy; s_u3[tid * 3 + 2] = uz;
        float xc = d * 0.5f;
        float env = 0.f;
        if (xc < 1.f) { float tt = 1.f - xc * xc; env = tt * tt; }
        g_env[e] = env;
        s_env[tid] = env;
        float pref = env * inv;
        float ang = PI_F * xc;
        #pragma unroll
        for (int n = 1; n <= 8; n++) s_feat[tid][n - 1] = pref * __sinf((float)n * ang);
        float ssn = (species[sn] == 1) ? 1.f : 0.f;
        float src = (species[rc] == 1) ? 1.f : 0.f;
        s_feat[tid][8] = 1.f - ssn; s_feat[tid][9] = ssn;
        s_feat[tid][10] = 1.f - src; s_feat[tid][11] = src;
    }
    __syncthreads();

    // phase A: hidden = silu(feat @ W1)  (K=12, scalar fp32; one col per thread)
    {
        int h = tid;
        float w1r[12];
        #pragma unroll
        for (int k = 0; k < 12; k++) w1r[k] = W1[k * HH + h];
        #pragma unroll 4
        for (int i = 0; i < TLE; i++) {
            float acc = 0.f;
            #pragma unroll
            for (int k = 0; k < 12; k++) acc += s_feat[i][k] * w1r[k];
            s_hid[i * HID_S + h] = silu_f(acc);
        }
    }
    __syncthreads();

    // phase B: x = (hidden @ W_emb2) * env   (3xTF32, reduction-free)
    {
        float a2[2][1][4];
        int r0 = (warp >> 3) * 32, n0 = (warp & 7) * 8;
        gemm3<2, 1, 64, HID_S>(s_hid, r0, g_Whi + OFF_EMB2, g_Wlo + OFF_EMB2,
                               CC, n0, g, t, a2);
        #pragma unroll
        for (int m = 0; m < 2; m++)
            #pragma unroll
            for (int q = 0; q < 4; q++) {
                int r = r0 + m * 16 + g + ((q & 2) ? 8 : 0);
                int c = n0 + 2 * t + (q & 1);
                float x = a2[m][0][q] * s_env[r];
                s_x[r * X_S + c] = x;
                g_x[(e0 + r) * CC + c] = x;
            }
    }
    __syncthreads();

    // vinit: V = (x @ Wv) outer u
    {
        float av[2][1][4];
        int r0 = (warp >> 3) * 32, n0 = (warp & 7) * 8;
        gemm3<2, 1, 8, X_S>(s_x, r0, g_Whi + OFF_V, g_Wlo + OFF_V, CC, n0, g, t, av);
        #pragma unroll
        for (int m = 0; m < 2; m++)
            #pragma unroll
            for (int q = 0; q < 4; q++) {
                int r = r0 + m * 16 + g + ((q & 2) ? 8 : 0);
                int c = n0 + 2 * t + (q & 1);
                float v = av[m][0][q];
                int vb = ((e0 + r) * CC + c) * 3;
                g_V[vb + 0] = v * s_u3[r * 3 + 0];
                g_V[vb + 1] = v * s_u3[r * 3 + 1];
                g_V[vb + 2] = v * s_u3[r * 3 + 2];
            }
    }

    // scatter layer-0 density: w_e = x @ Wenv0
    {
        float as[2][1][4];
        int r0 = (warp >> 3) * 32, n0 = (warp & 7) * 8;
        gemm3<2, 1, 8, X_S>(s_x, r0, g_Whi + OFF_ENV, g_Wlo + OFF_ENV, CC, n0, g, t, as);
        #pragma unroll
        for (int m = 0; m < 2; m++)
            #pragma unroll
            for (int q = 0; q < 4; q++) {
                int r = r0 + m * 16 + g + ((q & 2) ? 8 : 0);
                int c = n0 + 2 * t + (q & 1);
                float v = as[m][0][q] * (1.f / 3.f);
                int sn = s_send[r];
                atomicAdd(&g_rho0a[sn * CC + c], v);
                int rb = (sn * CC + c) * 3;
                atomicAdd(&g_rho1a[rb + 0], v * s_u3[r * 3 + 0]);
                atomicAdd(&g_rho1a[rb + 1], v * s_u3[r * 3 + 1]);
                atomicAdd(&g_rho1a[rb + 2], v * s_u3[r * 3 + 2]);
            }
    }
}

// ============================================================
// K2: full layer — gather+TP, 3xTF32 MLP, mix, V update, epilogue
// ============================================================
__global__ __launch_bounds__(NTHR, 1) void k_layer(
    int loff1, int loff2, int loffm, int loffe,
    const float* __restrict__ Wout,
    const int* __restrict__ senders,
    const int* __restrict__ receivers,
    const float* __restrict__ rho0r,
    const float* __restrict__ rho1r,
    float* __restrict__ rho0w,
    float* __restrict__ rho1w,
    float* __restrict__ out,
    int mode)
{
    extern __shared__ float sm[];
    float* s_lat = sm;                    // [64][LAT_S]
    float* s_hid = sm + TLE * LAT_S;      // [64][HID_S]
    float* s_mix = s_hid;                 // overlay after phase2: [64][MIX_S]
    __shared__ int   s_send[TLE], s_recv[TLE];
    __shared__ float s_env[TLE], s_u3[TLE * 3];

    const int tid = threadIdx.x;
    const int warp = tid >> 5, lane = tid & 31;
    const int g = lane >> 2, t = lane & 3;
    const int e0 = blockIdx.x * TLE;

    if (tid < TLE) {
        int e = e0 + tid;
        s_send[tid] = senders[e];
        s_recv[tid] = receivers[e];
        s_env[tid] = g_env[e];
        s_u3[tid * 3 + 0] = g_u[e * 3 + 0];
        s_u3[tid * 3 + 1] = g_u[e * 3 + 1];
        s_u3[tid * 3 + 2] = g_u[e * 3 + 2];
    }
    __syncthreads();

    // ---- build lat_in = [x | tp_scal | rho0_e] ----
    #pragma unroll
    for (int q = 0; q < (TLE * CC) / NTHR; q++) {
        int idx = tid + NTHR * q;
        int i = idx >> 6, c = idx & 63;
        int e = e0 + i, sn = s_send[i];
        float xv = g_x[e * CC + c];
        float r0v = rho0r[sn * CC + c];
        int rb = (sn * CC + c) * 3;
        float r1x = rho1r[rb], r1y = rho1r[rb + 1], r1z = rho1r[rb + 2];
        int vb = (e * CC + c) * 3;
        float Vx = g_V[vb], Vy = g_V[vb + 1], Vz = g_V[vb + 2];
        s_lat[i * LAT_S + c]       = xv;
        s_lat[i * LAT_S + 64 + c]  = Vx * r1x + Vy * r1y + Vz * r1z;
        s_lat[i * LAT_S + 128 + c] = r0v;
    }
    __syncthreads();

    // ---- phase 1: hidden = silu(lat @ W1)  MT=4, NT=4 (32 cols/warp) ----
    {
        float c1[4][4][4];
        int n0 = warp * 32;
        gemm3<4, 4, 24, LAT_S>(s_lat, 0, g_Whi + loff1, g_Wlo + loff1,
                               HH, n0, g, t, c1);
        #pragma unroll
        for (int m = 0; m < 4; m++)
            #pragma unroll
            for (int j = 0; j < 4; j++) {
                int r = m * 16 + g;
                int c = n0 + 8 * j + 2 * t;
                s_hid[r * HID_S + c]           = silu_f(c1[m][j][0]);
                s_hid[r * HID_S + c + 1]       = silu_f(c1[m][j][1]);
                s_hid[(r + 8) * HID_S + c]     = silu_f(c1[m][j][2]);
                s_hid[(r + 8) * HID_S + c + 1] = silu_f(c1[m][j][3]);
            }
    }
    __syncthreads();

    // ---- phase 2: dx = hidden @ W2, direct (no reduction); x update ----
    {
        float a2[2][1][4];
        int r0 = (warp >> 3) * 32, n0 = (warp & 7) * 8;
        gemm3<2, 1, 64, HID_S>(s_hid, r0, g_Whi + loff2, g_Wlo + loff2,
                               CC, n0, g, t, a2);
        const float inv_s2 = 0.70710678118654752f;
        #pragma unroll
        for (int m = 0; m < 2; m++)
            #pragma unroll
            for (int q = 0; q < 4; q++) {
                int r = r0 + m * 16 + g + ((q & 2) ? 8 : 0);
                int c = n0 + 2 * t + (q & 1);
                float xn = (s_lat[r * LAT_S + c] + a2[m][0][q] * s_env[r]) * inv_s2;
                s_lat[r * LAT_S + c] = xn;
                g_x[(e0 + r) * CC + c] = xn;
            }
    }
    __syncthreads();

    if (mode == 0) {
        // ---- phase 3a: mix = x_new @ Wm  (N=128: 8 cols/warp, all 64 rows) ----
        {
            float am[4][1][4];
            int n0 = warp * 8;
            gemm3<4, 1, 8, LAT_S>(s_lat, 0, g_Whi + loffm, g_Wlo + loffm,
                                  2 * CC, n0, g, t, am);
            #pragma unroll
            for (int m = 0; m < 4; m++)
                #pragma unroll
                for (int q = 0; q < 4; q++) {
                    int r = m * 16 + g + ((q & 2) ? 8 : 0);
                    int c = n0 + 2 * t + (q & 1);
                    s_mix[r * MIX_S + c] = am[m][0][q];
                }
        }
        __syncthreads();

        // ---- phase 3b: V = mix1 * (V * rho0) + mix2 * cross(V, rho1) ----
        #pragma unroll
        for (int q = 0; q < (TLE * CC) / NTHR; q++) {
            int idx = tid + NTHR * q;
            int i = idx >> 6, c = idx & 63;
            int e = e0 + i, sn = s_send[i];
            int vb = (e * CC + c) * 3;
            float Vx = g_V[vb], Vy = g_V[vb + 1], Vz = g_V[vb + 2];
            int rb = (sn * CC + c) * 3;
            float r1x = rho1r[rb], r1y = rho1r[rb + 1], r1z = rho1r[rb + 2];
            float r0v = s_lat[i * LAT_S + 128 + c];
            float m1 = s_mix[i * MIX_S + c];
            float m2 = s_mix[i * MIX_S + 64 + c];
            float cx = Vy * r1z - Vz * r1y;
            float cy = Vz * r1x - Vx * r1z;
            float cz = Vx * r1y - Vy * r1x;
            g_V[vb + 0] = m1 * Vx * r0v + m2 * cx;
            g_V[vb + 1] = m1 * Vy * r0v + m2 * cy;
            g_V[vb + 2] = m1 * Vz * r0v + m2 * cz;
        }

        // ---- scatter next-layer density (uses x_new) ----
        {
            float as[2][1][4];
            int r0 = (warp >> 3) * 32, n0 = (warp & 7) * 8;
            gemm3<2, 1, 8, LAT_S>(s_lat, r0, g_Whi + loffe, g_Wlo + loffe,
                                  CC, n0, g, t, as);
            #pragma unroll
            for (int m = 0; m < 2; m++)
                #pragma unroll
                for (int q = 0; q < 4; q++) {
                    int r = r0 + m * 16 + g + ((q & 2) ? 8 : 0);
                    int c = n0 + 2 * t + (q & 1);
                    float v = as[m][0][q] * (1.f / 3.f);
                    int sn = s_send[r];
                    atomicAdd(&rho0w[sn * CC + c], v);
                    int rb = (sn * CC + c) * 3;
                    atomicAdd(&rho1w[rb + 0], v * s_u3[r * 3 + 0]);
                    atomicAdd(&rho1w[rb + 1], v * s_u3[r * 3 + 1]);
                    atomicAdd(&rho1w[rb + 2], v * s_u3[r * 3 + 2]);
                }
        }
    } else {
        // ---- final energy readout: e = (x@Wout)*env -> receivers ----
        int i = tid >> 3, k8 = tid & 7;
        float p = 0.f;
        #pragma unroll
        for (int q = 0; q < 8; q++) {
            int c = k8 + 8 * q;
            p += s_lat[i * LAT_S + c] * __ldg(&Wout[c]);
        }
        p += __shfl_xor_sync(0xffffffffu, p, 1);
        p += __shfl_xor_sync(0xffffffffu, p, 2);
        p += __shfl_xor_sync(0xffffffffu, p, 4);
        if ((tid & 7) == 0)
            atomicAdd(&out[s_recv[i]], p * s_env[i] * (1.f / 3.f));
    }
}

// ============================================================
extern "C" void kernel_launch(void* const* d_in, const int* in_sizes, int n_in,
                              void* d_out, int out_size)
{
    const float* pos     = (const float*)d_in[0];
    const float* W_emb1  = (const float*)d_in[1];
    const float* W_emb2  = (const float*)d_in[2];
    const float* W_v     = (const float*)d_in[3];
    const float* W_env   = (const float*)d_in[4];
    const float* W_lat1  = (const float*)d_in[5];
    const float* W_lat2  = (const float*)d_in[6];
    const float* W_mix   = (const float*)d_in[7];
    const float* W_out   = (const float*)d_in[8];
    const int*   species = (const int*)d_in[9];
    const int*   senders = (const int*)d_in[10];
    const int*   recv    = (const int*)d_in[11];
    float* out = (float*)d_out;

    const int smem_embed = (TLE * HID_S + TLE * X_S) * sizeof(float);   // 149504
    const int smem_layer = (TLE * LAT_S + TLE * HID_S) * sizeof(float); // 182272
    cudaFuncSetAttribute(k_embed, cudaFuncAttributeMaxDynamicSharedMemorySize, smem_embed);
    cudaFuncSetAttribute(k_layer, cudaFuncAttributeMaxDynamicSharedMemorySize, smem_layer);

    float* rho0a; cudaGetSymbolAddress((void**)&rho0a, g_rho0a);
    float* rho1a; cudaGetSymbolAddress((void**)&rho1a, g_rho1a);
    float* rho0b; cudaGetSymbolAddress((void**)&rho0b, g_rho0b);
    float* rho1b; cudaGetSymbolAddress((void**)&rho1b, g_rho1b);

    k_zero<<<(NN * CC * 3 + 255) / 256, 256>>>(out);
    k_prep<<<(TOTW + 255) / 256, 256>>>(W_emb2, W_v, W_env, W_lat1, W_lat2, W_mix);
    k_embed<<<NE / TLE, NTHR, smem_embed>>>(pos, species, senders, recv, W_emb1);

    // layer 0: read rhoA, scatter rhoB for layer 1
    k_layer<<<NE / TLE, NTHR, smem_layer>>>(
        OFF_LAT1, OFF_LAT2, OFF_MIX, OFF_ENV + CC * CC, nullptr,
        senders, recv, rho0a, rho1a, rho0b, rho1b, out, 0);
    // layer 1 (final): read rhoB, energy readout
    k_layer<<<NE / TLE, NTHR, smem_layer>>>(
        OFF_LAT1 + 192 * HH, OFF_LAT2 + HH * CC, OFF_MIX + CC * 2 * CC, 0, W_out,
        senders, recv, rho0b, rho1b, nullptr, nullptr, out, 1);
}